// round 12
// baseline (speedup 1.0000x reference)
#include <cuda_runtime.h>

#define HID   64
#define BATCH 16
#define SEQ   512
#define VOCAB 32000
#define NTOK  (BATCH * SEQ * 2)     // 16384
#define RPB   8                     // rows per rowvec block (1 per warp)
#define NRVB  (NTOK / RPB)          // 2048
#define ACH   64                    // accum chunks per batch (16 tokens each)

// Scratch (no device allocs allowed). Stale g_rowlist/g_slot entries are
// always valid indices; only g_cnt_v, g_acc, g_nrows are cleared per launch.
__device__ int   g_cnt_v[VOCAB];          // dedup flag (zeroed each launch)
__device__ int   g_slot[VOCAB];           // v -> worklist slot
__device__ int   g_rowlist[NTOK];         // distinct rows
__device__ int   g_nrows[1];
__device__ float g_rowvec[NTOK * HID];    // r_v = sos . E_v  (4 MB)
__device__ float g_acc[BATCH * HID];      // per-batch hidden (atomic target)

// ---------------------------------------------------------------- zero
__global__ __launch_bounds__(256) void zero_kernel() {
    const int i = blockIdx.x * 256 + threadIdx.x;
    if (i < VOCAB / 4)
        reinterpret_cast<int4*>(g_cnt_v)[i] = make_int4(0, 0, 0, 0);
    if (i < BATCH * HID / 4)
        reinterpret_cast<float4*>(g_acc)[i] = make_float4(0.f, 0.f, 0.f, 0.f);
    if (i == 0) g_nrows[0] = 0;
}

// ---------------------------------------------------------------- histogram
// First toucher of row v claims a worklist slot and records v -> slot.
__global__ __launch_bounds__(256) void hist_kernel(
    const int* __restrict__ s1, const int* __restrict__ s2)
{
    const int t = blockIdx.x * 256 + threadIdx.x;    // 0..16383
    const int b = t >> 10;
    const int l = t & 1023;
    const int v = (l < SEQ) ? s1[b * SEQ + l] : s2[b * SEQ + (l - SEQ)];
    if (atomicAdd(&g_cnt_v[v], 1) == 0) {
        const int pos = atomicAdd(&g_nrows[0], 1);
        g_rowlist[pos] = v;
        g_slot[v] = pos;
    }
}

// ---------------------------------------------------------------- rowvec
// WARP-PER-ROW (measured ~6.8 TB/s): lane loads float4 f = lane + 32j
// (warp-load = 512B contiguous) into ONE register float4. hg = lane&15
// fixed; w = (lane>>4) + 2j. shfl_xor(16) merges half-warps; 16 lanes
// store 256B coalesced.
__global__ __launch_bounds__(256) void rowvec_kernel(
    const float* __restrict__ embed,
    const float* __restrict__ sos)
{
    __shared__ float s_sos[HID];
    __shared__ int   s_row[RPB];

    const int tid  = threadIdx.x;
    const int base = blockIdx.x * RPB;

    if (base >= g_nrows[0]) return;          // block-level early exit

    if (tid < HID) s_sos[tid] = sos[tid];
    if (tid < RPB) s_row[tid] = g_rowlist[base + tid];  // stale-safe
    __syncthreads();

    const int wid  = tid >> 5;               // warp = row
    const int lane = tid & 31;
    const int wb   = lane >> 4;              // 0 or 1 (w parity)

    const float4* row = reinterpret_cast<const float4*>(embed)
                        + ((long long)s_row[wid] << 10);

    float4 acc = make_float4(0.f, 0.f, 0.f, 0.f);
    #pragma unroll
    for (int j = 0; j < 32; j++) {
        const float4 v = __ldg(&row[lane + (j << 5)]);
        const float  s = s_sos[wb + (j << 1)];
        acc.x = fmaf(s, v.x, acc.x); acc.y = fmaf(s, v.y, acc.y);
        acc.z = fmaf(s, v.z, acc.z); acc.w = fmaf(s, v.w, acc.w);
    }

    acc.x += __shfl_xor_sync(0xffffffffu, acc.x, 16);
    acc.y += __shfl_xor_sync(0xffffffffu, acc.y, 16);
    acc.z += __shfl_xor_sync(0xffffffffu, acc.z, 16);
    acc.w += __shfl_xor_sync(0xffffffffu, acc.w, 16);

    if (lane < 16)
        reinterpret_cast<float4*>(&g_rowvec[(base + wid) * HID])[lane] = acc;
}

// ---------------------------------------------------------------- accum
// 1024 blocks = 16 batches x 64 chunks of 16 tokens; ~7 blocks/SM resident
// so the 3-round latency chain (token -> slot -> rowvec) fully overlaps.
// One float4 load per thread, block-reduce, 64 atomicAdds per block
// (65K total over 1024 addresses -> negligible).
__global__ __launch_bounds__(256) void accum_kernel(
    const int* __restrict__ s1, const int* __restrict__ s2)
{
    __shared__ int    s_slot[16];
    __shared__ float4 s_red[256];

    const int tid   = threadIdx.x;
    const int b     = blockIdx.x >> 6;
    const int chunk = blockIdx.x & 63;

    if (tid < 16) {
        const int l = chunk * 16 + tid;           // 0..1023
        const int v = (l < SEQ) ? s1[b * SEQ + l]
                                : s2[b * SEQ + (l - SEQ)];
        s_slot[tid] = g_slot[v];
    }
    __syncthreads();

    const int tok = tid >> 4;
    const int hg  = tid & 15;
    s_red[tid] = __ldg(&reinterpret_cast<const float4*>(g_rowvec)
                           [s_slot[tok] * 16 + hg]);
    __syncthreads();

    if (tid < 16) {
        float4 sum = make_float4(0.f, 0.f, 0.f, 0.f);
        #pragma unroll
        for (int j = 0; j < 16; j++) {
            const float4 p = s_red[(j << 4) + tid];
            sum.x += p.x; sum.y += p.y; sum.z += p.z; sum.w += p.w;
        }
        float* dst = &g_acc[b * HID + (tid << 2)];
        atomicAdd(dst + 0, sum.x);
        atomicAdd(dst + 1, sum.y);
        atomicAdd(dst + 2, sum.z);
        atomicAdd(dst + 3, sum.w);
    }
}

// ---------------------------------------------------------------- MLP
// Warp-dot form, zero staging: 16 blocks x 1024 threads. Warp wid computes
// hidden units h = wid and wid+32 via direct COALESCED w1-row loads (2 k per
// lane) + shfl reduction (fixed order -> deterministic). Exactly two
// global-latency rounds end to end.
__global__ __launch_bounds__(1024) void mlp_kernel(
    const float* __restrict__ w1,
    const float* __restrict__ b1,
    const float* __restrict__ w2,
    const float* __restrict__ b2,
    float*       __restrict__ out)
{
    __shared__ float sh[HID];
    __shared__ float sx[HID];

    const int b    = blockIdx.x;
    const int tid  = threadIdx.x;
    const int wid  = tid >> 5;
    const int lane = tid & 31;

    if (tid < HID) sh[tid] = g_acc[b * HID + tid];
    __syncthreads();

    const float a0 = sh[lane];
    const float a1 = sh[lane + 32];

    #pragma unroll
    for (int t = 0; t < 2; t++) {
        const int h = wid + t * 32;
        float p = fmaf(__ldg(&w1[h * HID + lane]),      a0,
                       __ldg(&w1[h * HID + lane + 32]) * a1);
        #pragma unroll
        for (int o = 16; o; o >>= 1)
            p += __shfl_xor_sync(0xffffffffu, p, o);
        if (lane == 0) sx[h] = fmaxf(p + b1[h], 0.0f);
    }
    __syncthreads();

    if (wid < 2) {
        float p = fmaf(__ldg(&w2[wid * HID + lane]),      sx[lane],
                       __ldg(&w2[wid * HID + lane + 32]) * sx[lane + 32]);
        #pragma unroll
        for (int o = 16; o; o >>= 1)
            p += __shfl_xor_sync(0xffffffffu, p, o);
        if (lane == 0) out[b * 2 + wid] = p + b2[wid];
    }
}

extern "C" void kernel_launch(void* const* d_in, const int* in_sizes, int n_in,
                              void* d_out, int out_size)
{
    const int*   s1    = (const int*)  d_in[0];
    const int*   s2    = (const int*)  d_in[1];
    const float* embed = (const float*)d_in[2];
    const float* sos   = (const float*)d_in[3];
    const float* w1    = (const float*)d_in[4];
    const float* b1    = (const float*)d_in[5];
    const float* w2    = (const float*)d_in[6];
    const float* b2    = (const float*)d_in[7];
    float* out = (float*)d_out;

    zero_kernel<<<(VOCAB / 4 + 255) / 256, 256>>>();
    hist_kernel<<<NTOK / 256, 256>>>(s1, s2);
    rowvec_kernel<<<NRVB, 256>>>(embed, sos);
    accum_kernel<<<BATCH * ACH, 256>>>(s1, s2);
    mlp_kernel<<<BATCH, 1024>>>(w1, b1, w2, b2, out);
}

// round 13
// speedup vs baseline: 1.0336x; 1.0336x over previous
#include <cuda_runtime.h>

#define HID   64
#define BATCH 16
#define SEQ   512
#define VOCAB 32000
#define NTOK  (BATCH * SEQ * 2)     // 16384
#define K1_BLOCKS (NTOK / 8)        // 8 warps/block, warp per token -> 2048
#define K2_BLOCKS 512               // 16 batches x 32 chunks of 32 tokens
#define W1T_STRIDE 65

// Scratch (no device allocs). Static zero-init gives first-launch state;
// K2's last block restores invariants (g_acc=0, g_done=0, g_gen++) so every
// graph replay is self-consistent. g_tag uses generation tags => no zeroing.
__device__ int   g_tag[VOCAB];            // last generation that claimed v
__device__ int   g_gen[1];                // generation counter (bumped per launch)
__device__ int   g_done[1];               // K2 completion counter
__device__ float g_rowvec[VOCAB * HID];   // r_v = sos . E_v, keyed by v (8 MB)
__device__ float g_acc[BATCH * HID];      // per-batch hidden (atomic target)

// ---------------------------------------------------------------- K1: claim + rowvec
// Warp per token. Lane0 claims row v via generation atomicMax (first toucher
// wins; duplicates exit). Winner warp: 32 independent float4 loads (each
// warp-load = 512B contiguous), ONE register float4 accumulator
// (hg = lane&15 fixed, w = (lane>>4) + 2j), shfl_xor(16) merge, 16-lane
// 256B coalesced store into g_rowvec[v*HID].
__global__ __launch_bounds__(256) void rowvec_kernel(
    const int*   __restrict__ s1,
    const int*   __restrict__ s2,
    const float* __restrict__ embed,
    const float* __restrict__ sos)
{
    __shared__ float s_sos[HID];
    __shared__ int   s_tok[8];

    const int tid  = threadIdx.x;
    const int wid  = tid >> 5;
    const int lane = tid & 31;

    if (tid < HID) s_sos[tid] = sos[tid];
    if (tid < 8) {
        const int t = blockIdx.x * 8 + tid;       // 0..16383
        const int b = t >> 10;
        const int l = t & 1023;
        s_tok[tid] = (l < SEQ) ? s1[b * SEQ + l]
                               : s2[b * SEQ + (l - SEQ)];
    }
    __syncthreads();

    const int v = s_tok[wid];
    int claimed = 0;
    if (lane == 0) {
        const int gen = g_gen[0] + 1;             // constant within a launch
        claimed = (atomicMax(&g_tag[v], gen) < gen) ? 1 : 0;
    }
    claimed = __shfl_sync(0xffffffffu, claimed, 0);
    if (!claimed) return;                         // duplicate token

    const int wb = lane >> 4;                     // w parity
    const float4* row = reinterpret_cast<const float4*>(embed)
                        + ((long long)v << 10);

    float4 acc = make_float4(0.f, 0.f, 0.f, 0.f);
    #pragma unroll
    for (int j = 0; j < 32; j++) {
        const float4 x = __ldg(&row[lane + (j << 5)]);
        const float  s = s_sos[wb + (j << 1)];
        acc.x = fmaf(s, x.x, acc.x); acc.y = fmaf(s, x.y, acc.y);
        acc.z = fmaf(s, x.z, acc.z); acc.w = fmaf(s, x.w, acc.w);
    }
    acc.x += __shfl_xor_sync(0xffffffffu, acc.x, 16);
    acc.y += __shfl_xor_sync(0xffffffffu, acc.y, 16);
    acc.z += __shfl_xor_sync(0xffffffffu, acc.z, 16);
    acc.w += __shfl_xor_sync(0xffffffffu, acc.w, 16);

    if (lane < 16)
        reinterpret_cast<float4*>(&g_rowvec[(long long)v * HID])[lane] = acc;
}

// ---------------------------------------------------------------- K2: accum + MLP + cleanup
// 512 blocks = 16 batches x 32 chunks of 32 tokens. Per thread: 2 scattered
// float4 loads (token -> rowvec, only 2 dependent rounds), block-reduce,
// 64 atomicAdds/block into g_acc. Last finishing block (threadfence-
// reduction pattern) runs the full MLP for all 16 batches, writes out,
// zeroes g_acc, resets g_done, bumps g_gen.
__global__ __launch_bounds__(256) void accum_mlp_kernel(
    const int*   __restrict__ s1,
    const int*   __restrict__ s2,
    const float* __restrict__ w1,
    const float* __restrict__ b1,
    const float* __restrict__ w2,
    const float* __restrict__ b2,
    float*       __restrict__ out)
{
    __shared__ int    s_tok[32];
    __shared__ float4 s_red[256];
    __shared__ int    s_last;
    __shared__ float  w1t[HID * W1T_STRIDE];      // used by last block only
    __shared__ float  shh[BATCH * HID];
    __shared__ float  sxx[BATCH * HID];

    const int tid   = threadIdx.x;
    const int b     = blockIdx.x >> 5;
    const int chunk = blockIdx.x & 31;

    if (tid < 32) {
        const int l = chunk * 32 + tid;           // 0..1023
        s_tok[tid] = (l < SEQ) ? s1[b * SEQ + l]
                               : s2[b * SEQ + (l - SEQ)];
    }
    __syncthreads();

    const int hg = tid & 15;
    const int tg = tid >> 4;                      // 0..15
    const float4* rv = reinterpret_cast<const float4*>(g_rowvec);

    const float4 p0 = __ldg(&rv[(long long)s_tok[tg]      * 16 + hg]);
    const float4 p1 = __ldg(&rv[(long long)s_tok[tg + 16] * 16 + hg]);
    float4 a;
    a.x = p0.x + p1.x; a.y = p0.y + p1.y;
    a.z = p0.z + p1.z; a.w = p0.w + p1.w;
    s_red[tid] = a;
    __syncthreads();

    if (tid < 16) {
        float4 sum = make_float4(0.f, 0.f, 0.f, 0.f);
        #pragma unroll
        for (int j = 0; j < 16; j++) {
            const float4 p = s_red[(j << 4) + tid];
            sum.x += p.x; sum.y += p.y; sum.z += p.z; sum.w += p.w;
        }
        float* dst = &g_acc[b * HID + (tid << 2)];
        atomicAdd(dst + 0, sum.x);
        atomicAdd(dst + 1, sum.y);
        atomicAdd(dst + 2, sum.z);
        atomicAdd(dst + 3, sum.w);
    }
    __syncthreads();

    if (tid == 0) {
        __threadfence();                          // publish this block's adds
        s_last = (atomicAdd(&g_done[0], 1) == (int)gridDim.x - 1) ? 1 : 0;
    }
    __syncthreads();
    if (!s_last) return;

    // ---------------- last block: full MLP for all batches ----------------
    __threadfence();                              // acquire all blocks' adds

    // Stage w1 transposed (pad-65) + read accumulated hidden.
    #pragma unroll
    for (int j = 0; j < 16; j++) {
        const int idx = tid + 256 * j;            // 0..4095
        w1t[(idx & 63) * W1T_STRIDE + (idx >> 6)] = w1[idx];
    }
    #pragma unroll
    for (int j = 0; j < 4; j++) {
        const int id = tid + 256 * j;             // 0..1023
        shh[id] = g_acc[id];
    }
    __syncthreads();

    // Layer 1 + ReLU: 1024 outputs, 4 per thread.
    #pragma unroll
    for (int j = 0; j < 4; j++) {
        const int id = tid + 256 * j;
        const int bb = id >> 6;
        const int h  = id & 63;
        float sum = b1[h];
        const float* hb = &shh[bb * HID];
        #pragma unroll
        for (int k = 0; k < HID; k++)
            sum = fmaf(hb[k], w1t[k * W1T_STRIDE + h], sum);
        sxx[id] = fmaxf(sum, 0.0f);
    }
    __syncthreads();

    // Layer 2: 32 outputs.
    if (tid < BATCH * 2) {
        const int bb = tid >> 1;
        const int o  = tid & 1;
        float s = b2[o];
        #pragma unroll
        for (int k = 0; k < HID; k++)
            s = fmaf(sxx[bb * HID + k], w2[o * HID + k], s);
        out[bb * 2 + o] = s;
    }

    // Cleanup for the next replay.
    #pragma unroll
    for (int j = 0; j < 4; j++)
        g_acc[tid + 256 * j] = 0.0f;
    if (tid == 0) {
        g_done[0] = 0;
        g_gen[0] = g_gen[0] + 1;
    }
}

extern "C" void kernel_launch(void* const* d_in, const int* in_sizes, int n_in,
                              void* d_out, int out_size)
{
    const int*   s1    = (const int*)  d_in[0];
    const int*   s2    = (const int*)  d_in[1];
    const float* embed = (const float*)d_in[2];
    const float* sos   = (const float*)d_in[3];
    const float* w1    = (const float*)d_in[4];
    const float* b1    = (const float*)d_in[5];
    const float* w2    = (const float*)d_in[6];
    const float* b2    = (const float*)d_in[7];
    float* out = (float*)d_out;

    rowvec_kernel<<<K1_BLOCKS, 256>>>(s1, s2, embed, sos);
    accum_mlp_kernel<<<K2_BLOCKS, 256>>>(s1, s2, w1, b1, w2, b2, out);
}